// round 7
// baseline (speedup 1.0000x reference)
#include <cuda_runtime.h>
#include <cstdint>

#define BT20   2621440u     // B*20 (elements per head slab)
#define NROWS  131072u
#define TPB    64
#define ATPB   256

__device__ uint32_t g_mask[40u * NROWS];   // bit o of word [k*NROWS+b] = keep(k,b,o)

// ---- packed f32x2 helpers ----
__device__ __forceinline__ unsigned long long pack2(float lo, float hi) {
    unsigned long long r;
    asm("mov.b64 %0, {%1, %2};" : "=l"(r) : "f"(lo), "f"(hi));
    return r;
}
__device__ __forceinline__ void unpack2(unsigned long long v, float &lo, float &hi) {
    asm("mov.b64 {%0, %1}, %2;" : "=f"(lo), "=f"(hi) : "l"(v));
}
__device__ __forceinline__ void fma2(unsigned long long &d, unsigned long long a,
                                     unsigned long long b) {
    asm("fma.rn.f32x2 %0, %1, %2, %0;" : "+l"(d) : "l"(a), "l"(b));
}
__device__ __forceinline__ void add2(unsigned long long &d, unsigned long long a) {
    asm("add.rn.f32x2 %0, %0, %1;" : "+l"(d) : "l"(a));
}
__device__ __forceinline__ unsigned long long f2lo(const float4 &v) { return pack2(v.x, v.y); }
__device__ __forceinline__ unsigned long long f2hi(const float4 &v) { return pack2(v.z, v.w); }

// integer add on the FMA pipe (IMAD); 'one' is runtime-opaque
__device__ __forceinline__ uint32_t addm(uint32_t a, uint32_t b, uint32_t one) {
    uint32_t r;
    asm("mad.lo.u32 %0, %1, %2, %3;" : "=r"(r) : "r"(b), "r"(one), "r"(a));
    return r;
}
__device__ __forceinline__ uint32_t mullo(uint32_t a, uint32_t b) {
    uint32_t r; asm("mul.lo.u32 %0, %1, %2;" : "=r"(r) : "r"(a), "r"(b)); return r;
}
__device__ __forceinline__ uint32_t mulhi_(uint32_t a, uint32_t b) {
    uint32_t r; asm("mul.hi.u32 %0, %1, %2;" : "=r"(r) : "r"(a), "r"(b)); return r;
}

// ---- Threefry-2x32-20, key (0,42); returns ~(o0^o1) ----
__device__ __forceinline__ uint32_t tf_xnor(uint32_t x1_init, uint32_t one, uint32_t c13) {
    const uint32_t ks1 = 42u;
    const uint32_t ks2 = 0x1BD11BDAu ^ 42u;
    uint32_t x0 = 0u;
    uint32_t x1 = x1_init;        // = j + ks1
#define TF_R(r)  { x0 = addm(x0, x1, one); \
                   x1 = __funnelshift_l(x1, x1, (r)); x1 ^= x0; }
#define TF_R13M  { x0 = addm(x0, x1, one); \
                   uint32_t lo_ = mullo(x1, c13), hi_ = mulhi_(x1, c13); \
                   x1 = (lo_ | hi_) ^ x0; }
    TF_R13M        TF_R(15) TF_R(26) TF_R(6)
    x0 = addm(x0, one*ks1, one);  x1 = addm(x1, one*(ks2 + 1u), one);
    TF_R(17) TF_R(29) TF_R(16) TF_R(24)
    x0 = addm(x0, one*ks2, one);  x1 = addm(x1, one*2u, one);
    TF_R13M        TF_R(15) TF_R(26) TF_R(6)
    x1 = addm(x1, one*(ks1 + 3u), one);
    TF_R(17) TF_R(29) TF_R(16) TF_R(24)
    x0 = addm(x0, one*ks1, one);  x1 = addm(x1, one*(ks2 + 4u), one);
    TF_R13M        TF_R(15) TF_R(26) TF_R(6)
    x0 = addm(x0, one*ks2, one);  x1 = addm(x1, one*5u, one);
#undef TF_R
#undef TF_R13M
    return ~(x0 ^ x1);   // keep-bit in MSB
}

// ================= Kernel A: mask generation =================
__global__ __launch_bounds__(ATPB)
void mask_kernel(uint32_t one) {
    const unsigned idx = blockIdx.x * ATPB + threadIdx.x;   // k*NROWS + b
    const unsigned k = idx >> 17;
    const unsigned b = idx & (NROWS - 1u);
    const uint32_t c13 = one << 13;
    const uint32_t jk = k * BT20 + b * 20u + 42u;           // j + ks1 base
    uint32_t w = 0u;
    #pragma unroll
    for (int o = 0; o < 20; o++) {
        uint32_t t = tf_xnor(addm(jk, one*(uint32_t)o, one), one, c13);
        uint32_t bit = t >> 31;
        asm("mad.lo.u32 %0, %1, %2, %0;" : "+r"(w) : "r"(bit), "r"(one << o));
    }
    g_mask[idx] = w;
}

// keep-multiplier 2.0f / 0.0f from mask bit o
__device__ __forceinline__ float keepf(uint32_t m, int o) {
    return __uint_as_float((uint32_t)((int)(m << (31 - o)) >> 31) & 0x40000000u);
}

// trunk for one row: h2[30] packed f32x2
__device__ __forceinline__ void trunk_row(const float* __restrict__ x, unsigned row,
                                          const float* sW1, const float* sb1,
                                          unsigned long long* h2) {
    unsigned long long x2[10];
    const float4* xp = (const float4*)(x + (size_t)row * 20);
    #pragma unroll
    for (int i = 0; i < 5; i++) {
        float4 v = xp[i];
        x2[2*i]   = f2lo(v);
        x2[2*i+1] = f2hi(v);
    }
    #pragma unroll
    for (int i = 0; i < 30; i++) {
        unsigned long long a0 = 0ull, a1 = 0ull, a2 = 0ull, a3 = 0ull;
        const float4* w0 = (const float4*)(sW1 + (2*i)   * 20);
        const float4* w1 = (const float4*)(sW1 + (2*i+1) * 20);
        #pragma unroll
        for (int d = 0; d < 5; d++) {
            float4 v0 = w0[d], v1 = w1[d];
            fma2(a0, x2[2*d],   f2lo(v0));
            fma2(a2, x2[2*d+1], f2hi(v0));
            fma2(a1, x2[2*d],   f2lo(v1));
            fma2(a3, x2[2*d+1], f2hi(v1));
        }
        add2(a0, a2);
        add2(a1, a3);
        float s0a, s0b, s1a, s1b;
        unpack2(a0, s0a, s0b);
        unpack2(a1, s1a, s1b);
        h2[i] = pack2(fmaxf(s0a + s0b + sb1[2*i],   0.f),
                      fmaxf(s1a + s1b + sb1[2*i+1], 0.f));
    }
}

// one head, one output o, two rows, 4 accumulator chains per row
__device__ __forceinline__ void head_dot2(const float* sWh, int o,
                                          const unsigned long long* h2a,
                                          const unsigned long long* h2b,
                                          float bias, uint32_t m0, uint32_t m1,
                                          float &y0, float &y1) {
    const float4* w4 = (const float4*)(sWh + o * 60);
    unsigned long long c0 = 0ull, c1 = 0ull, c2 = 0ull, c3 = 0ull;   // row 0
    unsigned long long e0 = 0ull, e1 = 0ull, e2 = 0ull, e3 = 0ull;   // row 1
    #pragma unroll
    for (int d = 0; d < 15; d += 2) {
        float4 v = w4[d];
        unsigned long long lo = f2lo(v), hi = f2hi(v);
        fma2(c0, lo, h2a[2*d]);
        fma2(c1, hi, h2a[2*d+1]);
        fma2(e0, lo, h2b[2*d]);
        fma2(e1, hi, h2b[2*d+1]);
        if (d + 1 < 15) {
            float4 w = w4[d+1];
            unsigned long long lo2 = f2lo(w), hi2 = f2hi(w);
            fma2(c2, lo2, h2a[2*d+2]);
            fma2(c3, hi2, h2a[2*d+3]);
            fma2(e2, lo2, h2b[2*d+2]);
            fma2(e3, hi2, h2b[2*d+3]);
        }
    }
    add2(c0, c1); add2(c2, c3); add2(c0, c2);
    add2(e0, e1); add2(e2, e3); add2(e0, e2);
    float p, q;
    unpack2(c0, p, q);
    y0 = fmaxf(p + q + bias, 0.f) * keepf(m0, o);
    unpack2(e0, p, q);
    y1 = fmaxf(p + q + bias, 0.f) * keepf(m1, o);
}

// ================= Kernel B: fused MLP + mask apply (2 rows/thread) =========
__global__ __launch_bounds__(TPB, 6)
void mlp_kernel(const float* __restrict__ x,
                const float* __restrict__ W1,
                const float* __restrict__ b1,
                const float* __restrict__ Wh,
                const float* __restrict__ bh,
                float* __restrict__ out)
{
    __shared__ __align__(16) float sW1[1200];   // [60][20]
    __shared__           float sb1[64];
    __shared__ __align__(16) float sbh[800];    // [40][20]
    __shared__ __align__(16) float sWhA[1200];  // Wh[k]      [20][60]
    __shared__ __align__(16) float sWhB[1200];  // Wh[k+20]   [20][60]

    const int tid = threadIdx.x;

    for (int i = tid; i < 300; i += TPB)
        ((float4*)sW1)[i] = ((const float4*)W1)[i];
    for (int i = tid; i < 200; i += TPB)
        ((float4*)sbh)[i] = ((const float4*)bh)[i];
    if (tid < 60) sb1[tid] = b1[tid];
    __syncthreads();

    const unsigned b0  = blockIdx.x * 128u + (unsigned)tid;  // row 0
    const unsigned b1r = b0 + 64u;                           // row 1

    unsigned long long h2a[30], h2b[30];
    trunk_row(x, b0,  sW1, sb1, h2a);
    trunk_row(x, b1r, sW1, sb1, h2b);

    const unsigned baseA = b0  * 20u;
    const unsigned baseB = b1r * 20u;

    for (int k = 0; k < 20; k++) {
        const uint32_t mA0 = g_mask[(unsigned)k        * NROWS + b0];
        const uint32_t mA1 = g_mask[(unsigned)k        * NROWS + b1r];
        const uint32_t mB0 = g_mask[(unsigned)(k + 20) * NROWS + b0];
        const uint32_t mB1 = g_mask[(unsigned)(k + 20) * NROWS + b1r];

        __syncthreads();   // protect previous iteration's sWh reads
        const float4* srcA = (const float4*)(Wh + (size_t)k        * 1200);
        const float4* srcB = (const float4*)(Wh + (size_t)(k + 20) * 1200);
        for (int i = tid; i < 300; i += TPB) {
            ((float4*)sWhA)[i] = srcA[i];
            ((float4*)sWhB)[i] = srcB[i];
        }
        __syncthreads();

        #pragma unroll 1
        for (int oc = 0; oc < 5; oc++) {
            float yA0[4], yA1[4], yB0[4], yB1[4];
            #pragma unroll
            for (int u = 0; u < 4; u++) {
                const int o = oc * 4 + u;
                head_dot2(sWhA, o, h2a, h2b, sbh[k*20 + o],
                          mA0, mA1, yA0[u], yA1[u]);
                head_dot2(sWhB, o, h2a, h2b, sbh[(k+20)*20 + o],
                          mB0, mB1, yB0[u], yB1[u]);
            }
            *(float4*)(out + (size_t)k        * BT20 + baseA + oc * 4) =
                make_float4(yA0[0], yA0[1], yA0[2], yA0[3]);
            *(float4*)(out + (size_t)k        * BT20 + baseB + oc * 4) =
                make_float4(yA1[0], yA1[1], yA1[2], yA1[3]);
            *(float4*)(out + (size_t)(k + 20) * BT20 + baseA + oc * 4) =
                make_float4(yB0[0], yB0[1], yB0[2], yB0[3]);
            *(float4*)(out + (size_t)(k + 20) * BT20 + baseB + oc * 4) =
                make_float4(yB1[0], yB1[1], yB1[2], yB1[3]);
        }
    }
}

extern "C" void kernel_launch(void* const* d_in, const int* in_sizes, int n_in,
                              void* d_out, int out_size) {
    const float* x  = (const float*)d_in[0];   // [131072, 20]
    const float* W1 = (const float*)d_in[1];   // [60, 20]
    const float* b1 = (const float*)d_in[2];   // [60]
    const float* Wh = (const float*)d_in[3];   // [40, 20, 60]
    const float* bh = (const float*)d_in[4];   // [40, 20]
    float* out = (float*)d_out;                // [40, 131072, 1, 20]

    const int rows = in_sizes[0] / 20;         // 131072
    mask_kernel<<<(40u * NROWS) / ATPB, ATPB>>>(1u);
    mlp_kernel<<<rows / 128, TPB>>>(x, W1, b1, Wh, bh, out);
}

// round 8
// speedup vs baseline: 1.4071x; 1.4071x over previous
#include <cuda_runtime.h>
#include <cstdint>

#define BT20   2621440u     // B*20 (elements per head slab)
#define HALFN  52428800u    // 20*BT20
#define NROWS  131072u
#define TPB    64

// ---- packed f32x2 helpers ----
__device__ __forceinline__ unsigned long long pack2(float lo, float hi) {
    unsigned long long r;
    asm("mov.b64 %0, {%1, %2};" : "=l"(r) : "f"(lo), "f"(hi));
    return r;
}
__device__ __forceinline__ void unpack2(unsigned long long v, float &lo, float &hi) {
    asm("mov.b64 {%0, %1}, %2;" : "=f"(lo), "=f"(hi) : "l"(v));
}
__device__ __forceinline__ void fma2(unsigned long long &d, unsigned long long a,
                                     unsigned long long b) {
    asm("fma.rn.f32x2 %0, %1, %2, %0;" : "+l"(d) : "l"(a), "l"(b));
}
__device__ __forceinline__ void add2(unsigned long long &d, unsigned long long a) {
    asm("add.rn.f32x2 %0, %0, %1;" : "+l"(d) : "l"(a));
}
__device__ __forceinline__ unsigned long long f2lo(const float4 &v) { return pack2(v.x, v.y); }
__device__ __forceinline__ unsigned long long f2hi(const float4 &v) { return pack2(v.z, v.w); }

// integer add on the FMA pipe (IMAD); 'one' is runtime-opaque
__device__ __forceinline__ uint32_t addm(uint32_t a, uint32_t b, uint32_t one) {
    uint32_t r;
    asm("mad.lo.u32 %0, %1, %2, %3;" : "=r"(r) : "r"(b), "r"(one), "r"(a));
    return r;
}

// ---- Threefry-2x32-20, key (0,42); returns ~(o0^o1); keep-bit in MSB ----
// x0 round-adds ride the fma pipe (IMAD w/ opaque one); rest on alu.
__device__ __forceinline__ uint32_t tf_mix(uint32_t x1_init, uint32_t one) {
    const uint32_t ks1 = 42u;
    const uint32_t ks2 = 0x1BD11BDAu ^ 42u;
    uint32_t x1 = x1_init;          // c1 + ks1
    uint32_t x0 = x1;               // round 1 add with x0=0
    x1 = __funnelshift_l(x1, x1, 13) ^ x0;
#define TF_R(r)  { x0 = addm(x0, x1, one); \
                   x1 = __funnelshift_l(x1, x1, (r)); x1 ^= x0; }
    TF_R(15) TF_R(26) TF_R(6)
    x0 += ks1;  x1 += ks2 + 1u;
    TF_R(17) TF_R(29) TF_R(16) TF_R(24)
    x0 += ks2;  x1 += 2u;
    TF_R(13) TF_R(15) TF_R(26) TF_R(6)
    x1 += ks1 + 3u;
    TF_R(17) TF_R(29) TF_R(16) TF_R(24)
    x0 += ks1;  x1 += ks2 + 4u;
    TF_R(13) TF_R(15) TF_R(26) TF_R(6)
    x0 += ks2;  x1 += 5u;
#undef TF_R
    return ~(x0 ^ x1);
}

// keep-multiplier 2.0f / 0.0f from mask bit o
__device__ __forceinline__ float keepf(uint32_t m, int o) {
    return __uint_as_float((uint32_t)((int)(m << (31 - o)) >> 31) & 0x40000000u);
}

// ================= fused kernel: trunk + heads + inline dropout =============
__global__ __launch_bounds__(TPB, 8)
void fused_kernel(const float* __restrict__ x,
                  const float* __restrict__ W1,
                  const float* __restrict__ b1,
                  const float* __restrict__ Wh,
                  const float* __restrict__ bh,
                  float* __restrict__ out,
                  uint32_t one)
{
    __shared__ __align__(16) float sW1[1200];   // [60][20]
    __shared__           float sb1[64];
    __shared__ __align__(16) float sbh[800];    // [40][20]
    __shared__ __align__(16) float sWhA[1200];  // Wh[k]      [20][60]
    __shared__ __align__(16) float sWhB[1200];  // Wh[k+20]   [20][60]

    const int tid = threadIdx.x;

    for (int i = tid; i < 300; i += TPB)
        ((float4*)sW1)[i] = ((const float4*)W1)[i];
    for (int i = tid; i < 200; i += TPB)
        ((float4*)sbh)[i] = ((const float4*)bh)[i];
    if (tid < 60) sb1[tid] = b1[tid];
    __syncthreads();

    const unsigned b = blockIdx.x * TPB + (unsigned)tid;   // one row per thread
    const unsigned base_b = b * 20u;

    // ---- trunk: h = relu(W1 @ x + b1), packed as 30 f32x2 regs ----
    unsigned long long h2[30];
    {
        unsigned long long x2[10];
        const float4* xp = (const float4*)(x + (size_t)b * 20);
        #pragma unroll
        for (int i = 0; i < 5; i++) {
            float4 v = xp[i];
            x2[2*i]   = f2lo(v);
            x2[2*i+1] = f2hi(v);
        }
        #pragma unroll
        for (int i = 0; i < 30; i++) {
            unsigned long long a0 = 0ull, a1 = 0ull, a2 = 0ull, a3 = 0ull;
            const float4* w0 = (const float4*)(sW1 + (2*i)   * 20);
            const float4* w1 = (const float4*)(sW1 + (2*i+1) * 20);
            #pragma unroll
            for (int d = 0; d < 5; d++) {
                float4 v0 = w0[d], v1 = w1[d];
                fma2(a0, x2[2*d],   f2lo(v0));
                fma2(a2, x2[2*d+1], f2hi(v0));
                fma2(a1, x2[2*d],   f2lo(v1));
                fma2(a3, x2[2*d+1], f2hi(v1));
            }
            add2(a0, a2);
            add2(a1, a3);
            float s0a, s0b, s1a, s1b;
            unpack2(a0, s0a, s0b);
            unpack2(a1, s1a, s1b);
            h2[i] = pack2(fmaxf(s0a + s0b + sb1[2*i],   0.f),
                          fmaxf(s1a + s1b + sb1[2*i+1], 0.f));
        }
    }

    // ---- prologue: mask words for k = 0 pair ----
    uint32_t mA = 0u, mB = 0u;
    #pragma unroll
    for (int o = 0; o < 20; o++) {
        uint32_t jA = base_b + (unsigned)o + 42u;       // j + ks1
        mA |= (tf_mix(jA,         one) >> 31) << o;
        mB |= (tf_mix(jA + HALFN, one) >> 31) << o;
    }

    for (int k = 0; k < 20; k++) {
        __syncthreads();   // protect previous iteration's sWh reads
        const float4* srcA = (const float4*)(Wh + (size_t)k        * 1200);
        const float4* srcB = (const float4*)(Wh + (size_t)(k + 20) * 1200);
        for (int i = tid; i < 300; i += TPB) {
            ((float4*)sWhA)[i] = srcA[i];
            ((float4*)sWhB)[i] = srcB[i];
        }
        __syncthreads();

        // masks for the NEXT k pair, built during this k's GEMM
        uint32_t nA = 0u, nB = 0u;
        const uint32_t nbase = (unsigned)(k + 1) * BT20 + base_b + 42u;

        #pragma unroll 1
        for (int oc = 0; oc < 5; oc++) {
            float y0v[4], y1v[4];
            #pragma unroll
            for (int u = 0; u < 4; u++) {
                const int o = oc * 4 + u;
                const float4* wA4 = (const float4*)(sWhA + o * 60);
                const float4* wB4 = (const float4*)(sWhB + o * 60);
                unsigned long long a0 = 0ull, a0b = 0ull, a1 = 0ull, a1b = 0ull;
                #pragma unroll
                for (int d = 0; d < 15; d++) {
                    float4 va = wA4[d];
                    float4 vb = wB4[d];
                    fma2(a0,  f2lo(va), h2[2*d]);
                    fma2(a0b, f2hi(va), h2[2*d+1]);
                    fma2(a1,  f2lo(vb), h2[2*d]);
                    fma2(a1b, f2hi(vb), h2[2*d+1]);
                }
                add2(a0, a0b);
                add2(a1, a1b);
                float pA, qA, pB, qB;
                unpack2(a0, pA, qA);
                unpack2(a1, pB, qB);
                float accA = (pA + qA) + sbh[k*20 + o];
                float accB = (pB + qB) + sbh[(k+20)*20 + o];
                y0v[u] = fmaxf(accA, 0.f) * keepf(mA, o);
                y1v[u] = fmaxf(accB, 0.f) * keepf(mB, o);

                // 2 threefry blocks for next-k masks (no smem; fills stalls)
                uint32_t jn = nbase + (unsigned)o;
                nA |= (tf_mix(jn,         one) >> 31) << o;
                nB |= (tf_mix(jn + HALFN, one) >> 31) << o;
            }
            *(float4*)(out + (size_t)k        * BT20 + base_b + oc * 4) =
                make_float4(y0v[0], y0v[1], y0v[2], y0v[3]);
            *(float4*)(out + (size_t)(k + 20) * BT20 + base_b + oc * 4) =
                make_float4(y1v[0], y1v[1], y1v[2], y1v[3]);
        }
        mA = nA;
        mB = nB;
    }
}

extern "C" void kernel_launch(void* const* d_in, const int* in_sizes, int n_in,
                              void* d_out, int out_size) {
    const float* x  = (const float*)d_in[0];   // [131072, 20]
    const float* W1 = (const float*)d_in[1];   // [60, 20]
    const float* b1 = (const float*)d_in[2];   // [60]
    const float* Wh = (const float*)d_in[3];   // [40, 20, 60]
    const float* bh = (const float*)d_in[4];   // [40, 20]
    float* out = (float*)d_out;                // [40, 131072, 1, 20]

    const int rows = in_sizes[0] / 20;         // 131072
    fused_kernel<<<rows / TPB, TPB>>>(x, W1, b1, Wh, bh, out, 1u);
}